// round 5
// baseline (speedup 1.0000x reference)
#include <cuda_runtime.h>
#include <cstdint>
#include <math.h>

#define BB   4
#define CH   32
#define GCH  384
#define HH   224
#define WW   224
#define HW   50176
#define NPLANE 6422528        // 4*32*224*224
#define N4     1605632        // NPLANE/4
#define NT   448              // threads per prop CTA (14 warps)
#define WT   8                // steps per tile (= sync period)
#define NTILE 28              // 224/8
#define TSTR 240              // tile element stride (224 + 8 pad each side)
#define TOBN 1824             // tob buffer floats: max(224*8, 8*228)

// Scratch (static device globals)
__device__ __align__(16) float g_y32[NPLANE];        // conv1 output
__device__ __align__(16) float g_dirA[4 * NPLANE];   // pass-1 directional outputs
__device__ __align__(16) float g_dirB[4 * NPLANE];   // pass-2 directional outputs
__device__ __align__(16) float g_s1[NPLANE];         // max of pass-1

__device__ __forceinline__ void cpa4(unsigned int saddr, const float* g)
{
    asm volatile("cp.async.ca.shared.global [%0], [%1], 4;\n"
                 :: "r"(saddr), "l"(g));
}

// ---------------------------------------------------------------------------
// conv1: y [4,2,224,224] -> g_y32 [4,32,224,224], 3x3 same
// ---------------------------------------------------------------------------
__global__ void __launch_bounds__(224) conv1_kernel(
    const float* __restrict__ y, const float* __restrict__ w3)
{
    int b = blockIdx.x / HH;
    int h = blockIdx.x % HH;
    int tid = threadIdx.x;

    __shared__ float si[2][3][WW + 2];
    __shared__ float sw[32 * 2 * 9];

    for (int i = tid; i < 576; i += 224) sw[i] = w3[i];

    #pragma unroll
    for (int ic = 0; ic < 2; ic++)
        #pragma unroll
        for (int r = 0; r < 3; r++) {
            int hh = h + r - 1;
            float v = (hh >= 0 && hh < HH)
                        ? y[((size_t)(b * 2 + ic) * HH + hh) * WW + tid] : 0.f;
            si[ic][r][tid + 1] = v;
            if (tid < 2) si[ic][r][tid * (WW + 1)] = 0.f;
        }
    __syncthreads();

    float v[18];
    #pragma unroll
    for (int ic = 0; ic < 2; ic++)
        #pragma unroll
        for (int r = 0; r < 3; r++)
            #pragma unroll
            for (int dx = 0; dx < 3; dx++)
                v[ic * 9 + r * 3 + dx] = si[ic][r][tid + dx];

    for (int oc = 0; oc < 32; oc++) {
        float acc = 0.f;
        #pragma unroll
        for (int k = 0; k < 18; k++) acc = fmaf(v[k], sw[oc * 18 + k], acc);
        g_y32[((size_t)(b * 32 + oc) * HH + h) * WW + tid] = acc;
    }
}

// ---------------------------------------------------------------------------
// Propagation: overlapped-window shuffle scan.
// Warp w owns elements [16w, 16w+16); computes over window e = 16w-8+lane.
// 8 steps between CTA barriers via __shfl (valid region shrinks onto owned).
// dir map: 0=lr(hor,fwd) 1=rl(vert,rev) 2=du(vert,fwd) 3=ud(hor,rev)
// hor: scan along W, vector along H. vert: scan along H, vector along W.
// ---------------------------------------------------------------------------
__global__ void __launch_bounds__(NT, 2) prop_kernel(
    const float* __restrict__ gates, int pass)
{
    int pid = blockIdx.x;           // 0..511
    int d  = pid >> 7;
    int bc = pid & 127;
    int b  = bc >> 5;
    int c  = bc & 31;
    bool hor = (d == 0 || d == 3);
    bool rev = (d == 1 || d == 3);

    const float* xin = pass ? g_s1 : g_y32;
    const float* xp  = xin + (size_t)bc * HW;
    float*       op  = (pass ? g_dirB : g_dirA) + (size_t)(d * 128 + bc) * HW;
    const float* g1p = gates + ((size_t)b * GCH + d * 96 + c) * HW;
    const float* g2p = g1p + (size_t)32 * HW;
    const float* g3p = g1p + (size_t)64 * HW;
    const float* gp[4] = { xp, g1p, g2p, g3p };

    // tiles[buf][a][j][e+8]  (step-major per array, element padded by 8)
    __shared__ float tiles[2][4][WT][TSTR];   // 61440 B
    __shared__ float tob[2][TOBN];            // 14592 B (layout differs hor/vert)
    __shared__ float hline[2][TSTR];          // 1920 B

    int tid  = threadIdx.x;
    int lane = tid & 31;
    int w    = tid >> 5;                      // 0..13
    int e    = 16 * w - 8 + lane;             // -8 .. 231
    bool owned = (lane >= 8 && lane < 24);    // e in [16w, 16w+16) ⊂ [0,224)

    // zero hline (both buffers incl. pads) and tile pads
    for (int i = tid; i < 2 * TSTR; i += NT) ((float*)hline)[i] = 0.f;
    for (int i = tid; i < 2 * 4 * WT * 16; i += NT) {
        int col = i & 15;
        int r   = i >> 4;
        int j   = r & 7;  r >>= 3;
        int a   = r & 3;
        int buf = r >> 2;
        tiles[buf][a][j][(col < 8) ? col : (col + 224)] = 0.f;
    }

    auto prefetch = [&](int tb, int buf) {
        if (hor) {
            #pragma unroll
            for (int i = 0; i < 4; i++) {
                int idx = i * NT + tid;       // 0..1791
                int s = idx >> 3, j = idx & 7;
                int tg = rev ? (223 - tb * WT - j) : (tb * WT + j);
                int off = s * WW + tg;
                #pragma unroll
                for (int a = 0; a < 4; a++)
                    cpa4((unsigned int)__cvta_generic_to_shared(
                             &tiles[buf][a][j][s + 8]), gp[a] + off);
            }
        } else {
            #pragma unroll
            for (int i = 0; i < 4; i++) {
                int idx = i * NT + tid;
                int j = idx / 224, s = idx % 224;
                int tg = rev ? (223 - tb * WT - j) : (tb * WT + j);
                int off = tg * WW + s;
                #pragma unroll
                for (int a = 0; a < 4; a++)
                    cpa4((unsigned int)__cvta_generic_to_shared(
                             &tiles[buf][a][j][s + 8]), gp[a] + off);
            }
        }
        asm volatile("cp.async.commit_group;");
    };

    auto flush = [&](int tb, int buf) {
        if (hor) {
            // tob layout: [e][8]
            #pragma unroll
            for (int i = 0; i < 4; i++) {
                int idx = i * NT + tid;
                int s = idx >> 3, j = idx & 7;
                int tg = rev ? (223 - tb * WT - j) : (tb * WT + j);
                op[s * WW + tg] = tob[buf][s * 8 + j];
            }
        } else {
            // tob layout: [j][228]
            #pragma unroll
            for (int i = 0; i < 4; i++) {
                int idx = i * NT + tid;
                int j = idx / 224, s = idx % 224;
                int tg = rev ? (223 - tb * WT - j) : (tb * WT + j);
                op[tg * WW + s] = tob[buf][j * 228 + s];
            }
        }
    };

    prefetch(0, 0);

    float h = 0.f;
    for (int tb = 0; tb < NTILE; tb++) {
        asm volatile("cp.async.wait_group 0;");
        __syncthreads();   // tile tb visible; all smem handoffs ordered

        if (tb + 1 < NTILE) prefetch(tb + 1, (tb + 1) & 1);
        if (tb > 0)         flush(tb - 1, (tb - 1) & 1);

        h = hline[tb & 1][e + 8];

        const float* tx = tiles[tb & 1][0][0];
        const float* t1 = tiles[tb & 1][1][0];
        const float* t2 = tiles[tb & 1][2][0];
        const float* t3 = tiles[tb & 1][3][0];
        int cb = tb & 1;
        int me = e + 8;

        #pragma unroll
        for (int j = 0; j < WT; j++) {
            int m = j * TSTR + me;
            float a1 = t1[m], a2 = t2[m], a3 = t3[m], xv = tx[m];
            float inv = __fdividef(1.0f,
                          fmaxf(fabsf(a1) + fabsf(a2) + fabsf(a3), 1.0f));
            float s1 = a1 * inv, s2 = a2 * inv, s3 = a3 * inv;
            float base = (1.0f - (a1 + a2 + a3) * inv) * xv;

            float hu = __shfl_up_sync(0xffffffffu, h, 1);
            float hd = __shfl_down_sync(0xffffffffu, h, 1);
            h = fmaf(s1, hu, fmaf(s2, h, fmaf(s3, hd, base)));

            if (owned) {
                if (hor) tob[cb][e * 8 + j] = h;
                else     tob[cb][j * 228 + e] = h;
            }
        }

        if (owned) hline[(tb + 1) & 1][e + 8] = h;
    }

    __syncthreads();
    flush(NTILE - 1, (NTILE - 1) & 1);
}

// ---------------------------------------------------------------------------
// max over 4 pass-1 direction buffers -> g_s1
// ---------------------------------------------------------------------------
__global__ void max_kernel()
{
    int i = blockIdx.x * blockDim.x + threadIdx.x;
    if (i >= N4) return;
    const float4* d0 = (const float4*)g_dirA;
    float4 a = d0[i];
    float4 b = d0[i + N4];
    float4 c = d0[i + 2 * N4];
    float4 e = d0[i + 3 * N4];
    float4 r;
    r.x = fmaxf(fmaxf(a.x, b.x), fmaxf(c.x, e.x));
    r.y = fmaxf(fmaxf(a.y, b.y), fmaxf(c.y, e.y));
    r.z = fmaxf(fmaxf(a.z, b.z), fmaxf(c.z, e.z));
    r.w = fmaxf(fmaxf(a.w, b.w), fmaxf(c.w, e.w));
    ((float4*)g_s1)[i] = r;
}

// ---------------------------------------------------------------------------
// conv2 (32->2, 3x3 same) fused with max over 4 pass-2 dirs + log_softmax
// ---------------------------------------------------------------------------
__global__ void __launch_bounds__(224) conv2_ls_kernel(
    const float* __restrict__ w4, float* __restrict__ out)
{
    int b = blockIdx.x / HH;
    int h = blockIdx.x % HH;
    int tid = threadIdx.x;

    __shared__ float si[16][3][WW + 2];
    __shared__ float sw[2 * 32 * 9];

    for (int i = tid; i < 576; i += 224) sw[i] = w4[i];

    float acc0 = 0.f, acc1 = 0.f;

    for (int chunk = 0; chunk < 2; chunk++) {
        __syncthreads();
        for (int icl = 0; icl < 16; icl++) {
            int ic = chunk * 16 + icl;
            #pragma unroll
            for (int r = 0; r < 3; r++) {
                int hh = h + r - 1;
                float v = 0.f;
                if (hh >= 0 && hh < HH) {
                    size_t base = ((size_t)(b * 32 + ic) * HH + hh) * WW + tid;
                    float v0 = g_dirB[base];
                    float v1 = g_dirB[base + 1 * (size_t)NPLANE];
                    float v2 = g_dirB[base + 2 * (size_t)NPLANE];
                    float v3 = g_dirB[base + 3 * (size_t)NPLANE];
                    v = fmaxf(fmaxf(v0, v1), fmaxf(v2, v3));
                }
                si[icl][r][tid + 1] = v;
                if (tid < 2) si[icl][r][tid * (WW + 1)] = 0.f;
            }
        }
        __syncthreads();
        for (int icl = 0; icl < 16; icl++) {
            int ic = chunk * 16 + icl;
            #pragma unroll
            for (int r = 0; r < 3; r++)
                #pragma unroll
                for (int dx = 0; dx < 3; dx++) {
                    float v = si[icl][r][tid + dx];
                    int k = ic * 9 + r * 3 + dx;
                    acc0 = fmaf(v, sw[k], acc0);
                    acc1 = fmaf(v, sw[288 + k], acc1);
                }
        }
    }

    float m  = fmaxf(acc0, acc1);
    float e0 = __expf(acc0 - m), e1 = __expf(acc1 - m);
    float lse = m + __logf(e0 + e1);
    size_t o = ((size_t)b * 2 * HH + h) * WW + tid;
    out[o]      = acc0 - lse;
    out[o + HW] = acc1 - lse;
}

// ---------------------------------------------------------------------------
extern "C" void kernel_launch(void* const* d_in, const int* in_sizes, int n_in,
                              void* d_out, int out_size)
{
    const float* gates = (const float*)d_in[0];  // [4,384,224,224]
    const float* y     = (const float*)d_in[1];  // [4,2,224,224]
    const float* w3    = (const float*)d_in[2];  // [32,2,3,3]
    const float* w4    = (const float*)d_in[3];  // [2,32,3,3]
    float* out = (float*)d_out;                  // [4,2,224,224]

    (void)in_sizes; (void)n_in; (void)out_size;

    conv1_kernel<<<BB * HH, 224>>>(y, w3);
    prop_kernel<<<512, NT>>>(gates, 0);      // -> g_dirA
    max_kernel<<<(N4 + 255) / 256, 256>>>(); // g_dirA -> g_s1
    prop_kernel<<<512, NT>>>(gates, 1);      // x=g_s1 -> g_dirB
    conv2_ls_kernel<<<BB * HH, 224>>>(w4, out);
}

// round 6
// speedup vs baseline: 1.3252x; 1.3252x over previous
#include <cuda_runtime.h>
#include <cstdint>
#include <math.h>

#define BB   4
#define CH   32
#define GCH  384
#define HH   224
#define WW   224
#define HW   50176
#define NPLANE 6422528        // 4*32*224*224
#define N4     1605632        // NPLANE/4
#define WT   8                // scan tile width (steps per SMEM tile)
#define SSTR 233              // padded SMEM row stride
#define NTB  28               // 224/8

// Scratch (static device globals)
__device__ __align__(16) float g_y32[NPLANE];        // conv1 output
__device__ __align__(16) float g_dirA[4 * NPLANE];   // pass-1 directional outputs
__device__ __align__(16) float g_dirB[4 * NPLANE];   // pass-2 directional outputs
__device__ __align__(16) float g_s1[NPLANE];         // max of pass-1

// ---------------------------------------------------------------------------
// conv1: y [4,2,224,224] -> g_y32 [4,32,224,224], 3x3 same
// ---------------------------------------------------------------------------
__global__ void __launch_bounds__(224) conv1_kernel(
    const float* __restrict__ y, const float* __restrict__ w3)
{
    int b = blockIdx.x / HH;
    int h = blockIdx.x % HH;
    int tid = threadIdx.x;

    __shared__ float si[2][3][WW + 2];
    __shared__ float sw[32 * 2 * 9];

    for (int i = tid; i < 576; i += 224) sw[i] = w3[i];

    #pragma unroll
    for (int ic = 0; ic < 2; ic++)
        #pragma unroll
        for (int r = 0; r < 3; r++) {
            int hh = h + r - 1;
            float v = (hh >= 0 && hh < HH)
                        ? y[((size_t)(b * 2 + ic) * HH + hh) * WW + tid] : 0.f;
            si[ic][r][tid + 1] = v;
            if (tid < 2) si[ic][r][tid * (WW + 1)] = 0.f;
        }
    __syncthreads();

    float v[18];
    #pragma unroll
    for (int ic = 0; ic < 2; ic++)
        #pragma unroll
        for (int r = 0; r < 3; r++)
            #pragma unroll
            for (int dx = 0; dx < 3; dx++)
                v[ic * 9 + r * 3 + dx] = si[ic][r][tid + dx];

    for (int oc = 0; oc < 32; oc++) {
        float acc = 0.f;
        #pragma unroll
        for (int k = 0; k < 18; k++) acc = fmaf(v[k], sw[oc * 18 + k], acc);
        g_y32[((size_t)(b * 32 + oc) * HH + h) * WW + tid] = acc;
    }
}

// ---------------------------------------------------------------------------
// Propagation (R1 structure + 4 CTAs/SM + L2 prefetch of next tile).
// One CTA per (direction, b, c) plane; 224 threads = vector dim.
// dir map: 0=lr(hor,fwd) 1=rl(vert,rev) 2=du(vert,fwd) 3=ud(hor,rev)
// ---------------------------------------------------------------------------
__global__ void __launch_bounds__(224, 4) prop_kernel(
    const float* __restrict__ gates, int pass)
{
    int pid = blockIdx.x;           // 0..511
    int d  = pid >> 7;
    int bc = pid & 127;
    int b  = bc >> 5;
    int c  = bc & 31;
    bool hor = (d == 0 || d == 3);
    bool rev = (d == 1 || d == 3);

    const float* xin = pass ? g_s1 : g_y32;
    const float* xp  = xin + (size_t)bc * HW;
    float*       op  = (pass ? g_dirB : g_dirA) + (size_t)(d * 128 + bc) * HW;
    const float* g1p = gates + ((size_t)b * GCH + d * 96 + c) * HW;
    const float* g2p = g1p + (size_t)32 * HW;
    const float* g3p = g1p + (size_t)64 * HW;
    const float* gp[4] = { xp, g1p, g2p, g3p };

    __shared__ float tx[WT * SSTR], t1[WT * SSTR], t2[WT * SSTR],
                     t3[WT * SSTR], to[WT * SSTR];
    __shared__ float hb[2][WW + 2];

    int tid = threadIdx.x;
    for (int i = tid; i < 2 * (WW + 2); i += 224) ((float*)hb)[i] = 0.f;

    // Warm L2 with tile 0
    {
        if (hor) {
            int tgs = rev ? 216 : 0;
            int off = tid * WW + tgs;
            #pragma unroll
            for (int a = 0; a < 4; a++)
                asm volatile("prefetch.global.L2 [%0];" :: "l"(gp[a] + off));
        } else {
            int j = tid / 28, sec = tid % 28;
            int tg = rev ? (223 - j) : j;
            int off = tg * WW + sec * 8;
            #pragma unroll
            for (int a = 0; a < 4; a++)
                asm volatile("prefetch.global.L2 [%0];" :: "l"(gp[a] + off));
        }
    }

    float hreg = 0.f;

    for (int tb = 0; tb < NTB; tb++) {
        int t0 = tb * WT;

        // ---- load x,g1,g2,g3 tiles (coalesced, 32B groups) ----
        if (hor) {
            #pragma unroll
            for (int i = 0; i < WT; i++) {
                int idx = i * 224 + tid;
                int s = idx >> 3, j = idx & 7;
                int tg = rev ? (223 - t0 - j) : (t0 + j);
                int off = s * WW + tg;
                int m = j * SSTR + s;
                tx[m] = xp[off];  t1[m] = g1p[off];
                t2[m] = g2p[off]; t3[m] = g3p[off];
            }
        } else {
            #pragma unroll
            for (int i = 0; i < WT; i++) {
                int tg = rev ? (223 - t0 - i) : (t0 + i);
                int off = tg * WW + tid;
                int m = i * SSTR + tid;
                tx[m] = xp[off];  t1[m] = g1p[off];
                t2[m] = g2p[off]; t3[m] = g3p[off];
            }
        }

        // ---- L2-prefetch tile tb+1 (covers the scan phase latency) ----
        if (tb + 1 < NTB) {
            int t0n = t0 + WT;
            if (hor) {
                int tgs = rev ? (216 - t0n) : t0n;   // 32B-aligned group start
                int off = tid * WW + tgs;
                #pragma unroll
                for (int a = 0; a < 4; a++)
                    asm volatile("prefetch.global.L2 [%0];" :: "l"(gp[a] + off));
            } else {
                int j = tid / 28, sec = tid % 28;
                int tg = rev ? (223 - t0n - j) : (t0n + j);
                int off = tg * WW + sec * 8;
                #pragma unroll
                for (int a = 0; a < 4; a++)
                    asm volatile("prefetch.global.L2 [%0];" :: "l"(gp[a] + off));
            }
        }
        __syncthreads();

        // ---- serial scan over WT steps ----
        #pragma unroll
        for (int j = 0; j < WT; j++) {
            int t = t0 + j;
            const float* hp = hb[t & 1];
            float*       hc = hb[(t & 1) ^ 1];
            int m = j * SSTR + tid;
            float xv = tx[m], a1 = t1[m], a2 = t2[m], a3 = t3[m];
            float sa = fabsf(a1) + fabsf(a2) + fabsf(a3);
            float inv = __fdividef(1.0f, fmaxf(sa, 1.0f));
            a1 *= inv; a2 *= inv; a3 *= inv;
            float hn = (1.0f - a1 - a2 - a3) * xv
                     + a1 * hp[tid] + a2 * hreg + a3 * hp[tid + 2];
            hc[tid + 1] = hn;
            to[m] = hn;
            hreg = hn;
            __syncthreads();
        }

        // ---- flush output tile (coalesced stores) ----
        if (hor) {
            #pragma unroll
            for (int i = 0; i < WT; i++) {
                int idx = i * 224 + tid;
                int s = idx >> 3, j = idx & 7;
                int tg = rev ? (223 - t0 - j) : (t0 + j);
                op[s * WW + tg] = to[j * SSTR + s];
            }
        } else {
            #pragma unroll
            for (int i = 0; i < WT; i++) {
                int tg = rev ? (223 - t0 - i) : (t0 + i);
                op[tg * WW + tid] = to[i * SSTR + tid];
            }
        }
        // next tile's load-sync orders flush reads before `to` is rewritten
    }
}

// ---------------------------------------------------------------------------
// max over 4 pass-1 direction buffers -> g_s1
// ---------------------------------------------------------------------------
__global__ void max_kernel()
{
    int i = blockIdx.x * blockDim.x + threadIdx.x;
    if (i >= N4) return;
    const float4* d0 = (const float4*)g_dirA;
    float4 a = d0[i];
    float4 b = d0[i + N4];
    float4 c = d0[i + 2 * N4];
    float4 e = d0[i + 3 * N4];
    float4 r;
    r.x = fmaxf(fmaxf(a.x, b.x), fmaxf(c.x, e.x));
    r.y = fmaxf(fmaxf(a.y, b.y), fmaxf(c.y, e.y));
    r.z = fmaxf(fmaxf(a.z, b.z), fmaxf(c.z, e.z));
    r.w = fmaxf(fmaxf(a.w, b.w), fmaxf(c.w, e.w));
    ((float4*)g_s1)[i] = r;
}

// ---------------------------------------------------------------------------
// conv2 (32->2, 3x3 same) fused with max over 4 pass-2 dirs + log_softmax
// ---------------------------------------------------------------------------
__global__ void __launch_bounds__(224) conv2_ls_kernel(
    const float* __restrict__ w4, float* __restrict__ out)
{
    int b = blockIdx.x / HH;
    int h = blockIdx.x % HH;
    int tid = threadIdx.x;

    __shared__ float si[16][3][WW + 2];
    __shared__ float sw[2 * 32 * 9];

    for (int i = tid; i < 576; i += 224) sw[i] = w4[i];

    float acc0 = 0.f, acc1 = 0.f;

    for (int chunk = 0; chunk < 2; chunk++) {
        __syncthreads();
        for (int icl = 0; icl < 16; icl++) {
            int ic = chunk * 16 + icl;
            #pragma unroll
            for (int r = 0; r < 3; r++) {
                int hh = h + r - 1;
                float v = 0.f;
                if (hh >= 0 && hh < HH) {
                    size_t base = ((size_t)(b * 32 + ic) * HH + hh) * WW + tid;
                    float v0 = g_dirB[base];
                    float v1 = g_dirB[base + 1 * (size_t)NPLANE];
                    float v2 = g_dirB[base + 2 * (size_t)NPLANE];
                    float v3 = g_dirB[base + 3 * (size_t)NPLANE];
                    v = fmaxf(fmaxf(v0, v1), fmaxf(v2, v3));
                }
                si[icl][r][tid + 1] = v;
                if (tid < 2) si[icl][r][tid * (WW + 1)] = 0.f;
            }
        }
        __syncthreads();
        for (int icl = 0; icl < 16; icl++) {
            int ic = chunk * 16 + icl;
            #pragma unroll
            for (int r = 0; r < 3; r++)
                #pragma unroll
                for (int dx = 0; dx < 3; dx++) {
                    float v = si[icl][r][tid + dx];
                    int k = ic * 9 + r * 3 + dx;
                    acc0 = fmaf(v, sw[k], acc0);
                    acc1 = fmaf(v, sw[288 + k], acc1);
                }
        }
    }

    float m  = fmaxf(acc0, acc1);
    float e0 = __expf(acc0 - m), e1 = __expf(acc1 - m);
    float lse = m + __logf(e0 + e1);
    size_t o = ((size_t)b * 2 * HH + h) * WW + tid;
    out[o]      = acc0 - lse;
    out[o + HW] = acc1 - lse;
}

// ---------------------------------------------------------------------------
extern "C" void kernel_launch(void* const* d_in, const int* in_sizes, int n_in,
                              void* d_out, int out_size)
{
    const float* gates = (const float*)d_in[0];  // [4,384,224,224]
    const float* y     = (const float*)d_in[1];  // [4,2,224,224]
    const float* w3    = (const float*)d_in[2];  // [32,2,3,3]
    const float* w4    = (const float*)d_in[3];  // [2,32,3,3]
    float* out = (float*)d_out;                  // [4,2,224,224]

    (void)in_sizes; (void)n_in; (void)out_size;

    conv1_kernel<<<BB * HH, 224>>>(y, w3);
    prop_kernel<<<512, 224>>>(gates, 0);     // -> g_dirA
    max_kernel<<<(N4 + 255) / 256, 256>>>(); // g_dirA -> g_s1
    prop_kernel<<<512, 224>>>(gates, 1);     // x=g_s1 -> g_dirB
    conv2_ls_kernel<<<BB * HH, 224>>>(w4, out);
}